// round 2
// baseline (speedup 1.0000x reference)
#include <cuda_runtime.h>
#include <math.h>

#define B_SZ 512
#define D_SZ 512
#define C_SZ 100000
#define NTILE_N 64
#define NTILE_M 128
#define NT 1563              // ceil(C_SZ / 64)
#define S_SCALE 30.0f
#define COS_M 0.8775825618903728f
#define SIN_M 0.47942553860420300f

// Scratch (static device allocations — no cudaMalloc allowed)
__device__ float g_xn[B_SZ * D_SZ];
__device__ float g_winv[C_SZ];
__device__ float g_pmax[(size_t)B_SZ * NT];
__device__ float g_psum[(size_t)B_SZ * NT];
__device__ float g_nll[B_SZ];

// ---------------------------------------------------------------------------
// Kernel 1: L2-normalize x rows -> g_xn  (512 rows x 512)
// ---------------------------------------------------------------------------
__global__ void xnorm_kernel(const float* __restrict__ x) {
    const int row = blockIdx.x;
    const int tid = threadIdx.x;      // 128 threads
    const float* xr = x + (size_t)row * D_SZ;

    float ss = 0.f;
    #pragma unroll
    for (int i = 0; i < 4; i++) {
        float v = xr[tid + i * 128];
        ss += v * v;
    }
    __shared__ float red[128];
    red[tid] = ss;
    __syncthreads();
    #pragma unroll
    for (int off = 64; off > 0; off >>= 1) {
        if (tid < off) red[tid] += red[tid + off];
        __syncthreads();
    }
    const float inv = 1.f / fmaxf(sqrtf(red[0]), 1e-12f);
    #pragma unroll
    for (int i = 0; i < 4; i++) {
        int d = tid + i * 128;
        g_xn[(size_t)row * D_SZ + d] = xr[d] * inv;
    }
}

// ---------------------------------------------------------------------------
// Kernel 2: inverse L2 norms of weight rows -> g_winv (one warp per row)
// ---------------------------------------------------------------------------
__global__ void wnorm_kernel(const float* __restrict__ w) {
    const int warp = threadIdx.x >> 5;
    const int lane = threadIdx.x & 31;
    const int c = blockIdx.x * 8 + warp;           // C_SZ = 12500 * 8 exactly
    const float4* wr = reinterpret_cast<const float4*>(w + (size_t)c * D_SZ);

    float ss = 0.f;
    #pragma unroll
    for (int i = 0; i < 4; i++) {
        float4 v = wr[lane + i * 32];
        ss += v.x * v.x + v.y * v.y + v.z * v.z + v.w * v.w;
    }
    #pragma unroll
    for (int m = 16; m > 0; m >>= 1)
        ss += __shfl_xor_sync(0xffffffffu, ss, m);
    if (lane == 0)
        g_winv[c] = 1.f / fmaxf(sqrtf(ss), 1e-12f);
}

// ---------------------------------------------------------------------------
// Kernel 3: fused GEMM tile (128 batch x 64 classes) + per-row streaming
//           softmax partials (max, sum-exp) written to g_pmax/g_psum.
// Thread layout: 256 threads = 16(tx, class dir) x 16(ty, batch dir),
// each thread owns 8 rows x 4 cols.
// ---------------------------------------------------------------------------
__global__ void __launch_bounds__(256) gemm_partial_kernel(const float* __restrict__ w) {
    __shared__ __align__(16) float As[16][132];   // [k][m], padded
    __shared__ __align__(16) float Bs[16][68];    // [k][n]

    const int ntile = blockIdx.x;
    const int mtile = blockIdx.y;
    const int c0 = ntile * NTILE_N;
    const int m0 = mtile * NTILE_M;
    const int tid = threadIdx.x;
    const int tx = tid & 15;
    const int ty = tid >> 4;

    float acc[8][4];
    #pragma unroll
    for (int i = 0; i < 8; i++)
        #pragma unroll
        for (int j = 0; j < 4; j++) acc[i][j] = 0.f;

    for (int k0 = 0; k0 < D_SZ; k0 += 16) {
        // load A tile: 128 rows x 16 k (transposed into As[k][m])
        #pragma unroll
        for (int i = 0; i < 8; i++) {
            int e = tid + i * 256;
            int k = e & 15, m = e >> 4;
            As[k][m] = g_xn[(size_t)(m0 + m) * D_SZ + k0 + k];
        }
        // load B tile: 64 classes x 16 k
        #pragma unroll
        for (int i = 0; i < 4; i++) {
            int e = tid + i * 256;
            int k = e & 15, c = e >> 4;
            int cc = c0 + c;
            Bs[k][c] = (cc < C_SZ) ? w[(size_t)cc * D_SZ + k0 + k] : 0.f;
        }
        __syncthreads();

        #pragma unroll
        for (int kk = 0; kk < 16; kk++) {
            float4 a0 = *reinterpret_cast<const float4*>(&As[kk][ty * 8]);
            float4 a1 = *reinterpret_cast<const float4*>(&As[kk][ty * 8 + 4]);
            float4 bv = *reinterpret_cast<const float4*>(&Bs[kk][tx * 4]);
            float a[8] = {a0.x, a0.y, a0.z, a0.w, a1.x, a1.y, a1.z, a1.w};
            float b[4] = {bv.x, bv.y, bv.z, bv.w};
            #pragma unroll
            for (int i = 0; i < 8; i++)
                #pragma unroll
                for (int j = 0; j < 4; j++)
                    acc[i][j] += a[i] * b[j];
        }
        __syncthreads();
    }

    // Epilogue: logits = S * cosine, per-row (max, sum-exp) over the 64-col tile
    const int cbase = c0 + tx * 4;
    float winv[4];
    #pragma unroll
    for (int j = 0; j < 4; j++)
        winv[j] = (cbase + j < C_SZ) ? g_winv[cbase + j] : 0.f;

    #pragma unroll
    for (int i = 0; i < 8; i++) {
        float l[4];
        float lmax = -INFINITY;
        #pragma unroll
        for (int j = 0; j < 4; j++) {
            l[j] = (cbase + j < C_SZ) ? S_SCALE * acc[i][j] * winv[j] : -INFINITY;
            lmax = fmaxf(lmax, l[j]);
        }
        // reduce across the 16 tx lanes (within each 16-lane half-warp)
        #pragma unroll
        for (int m = 8; m > 0; m >>= 1)
            lmax = fmaxf(lmax, __shfl_xor_sync(0xffffffffu, lmax, m));
        float lsum = 0.f;
        #pragma unroll
        for (int j = 0; j < 4; j++)
            if (cbase + j < C_SZ) lsum += __expf(l[j] - lmax);
        #pragma unroll
        for (int m = 8; m > 0; m >>= 1)
            lsum += __shfl_xor_sync(0xffffffffu, lsum, m);
        if (tx == 0) {
            int row = m0 + ty * 8 + i;
            g_pmax[(size_t)row * NT + ntile] = lmax;
            g_psum[(size_t)row * NT + ntile] = lsum;
        }
    }
}

// ---------------------------------------------------------------------------
// Kernel 4: per batch row — merge LSE partials, exact fp32 target dot,
//           ArcFace margin correction, nll.
// NOTE: target is int32 (JAX x64 disabled downcasts jnp.int64 -> int32).
// ---------------------------------------------------------------------------
__global__ void finalize_kernel(const float* __restrict__ w,
                                const int* __restrict__ tgt) {
    const int b = blockIdx.x;
    const int tid = threadIdx.x;   // 256

    // per-thread online LSE merge over strided tiles
    float m = -INFINITY, s = 0.f;
    const float* pm = g_pmax + (size_t)b * NT;
    const float* ps = g_psum + (size_t)b * NT;
    for (int t = tid; t < NT; t += 256) {
        float mi = pm[t], si = ps[t];
        if (mi > m) {
            s = s * __expf(m - mi) + si;
            m = mi;
        } else {
            s += si * __expf(mi - m);
        }
    }

    __shared__ float sm[256], ssm[256];
    sm[tid] = m; ssm[tid] = s;
    __syncthreads();
    #pragma unroll
    for (int off = 128; off > 0; off >>= 1) {
        if (tid < off) {
            float m1 = sm[tid], m2 = sm[tid + off];
            float s1 = ssm[tid], s2 = ssm[tid + off];
            float mm = fmaxf(m1, m2);
            sm[tid] = mm;
            ssm[tid] = s1 * __expf(m1 - mm) + s2 * __expf(m2 - mm);
        }
        __syncthreads();
    }
    const float M = sm[0];
    const float SUM = ssm[0];
    __syncthreads();

    // exact fp32 dot(xn[b], w[target]) for the margin term
    const int t = tgt[b];
    const float* wr = w + (size_t)t * D_SZ;
    const float* xr = g_xn + (size_t)b * D_SZ;
    float dp = xr[tid] * wr[tid] + xr[tid + 256] * wr[tid + 256];
    sm[tid] = dp;
    __syncthreads();
    #pragma unroll
    for (int off = 128; off > 0; off >>= 1) {
        if (tid < off) sm[tid] += sm[tid + off];
        __syncthreads();
    }

    if (tid == 0) {
        float cosv = sm[0] * g_winv[t];
        float sinv = sqrtf(fmaxf(1.f - cosv * cosv, 0.f));
        float phi = cosv * COS_M - sinv * SIN_M;
        float adj = (cosv > 0.f) ? phi : cosv;   // easy margin
        float lt = S_SCALE * adj;
        float lo = S_SCALE * cosv;
        float s2 = SUM - expf(lo - M) + expf(lt - M);
        g_nll[b] = M + logf(s2) - lt;
    }
}

// ---------------------------------------------------------------------------
// Kernel 5: mean over batch -> d_out[0]
// ---------------------------------------------------------------------------
__global__ void mean_kernel(float* __restrict__ out) {
    const int tid = threadIdx.x;   // 256
    __shared__ float sm[256];
    float v = g_nll[tid] + g_nll[tid + 256];
    sm[tid] = v;
    __syncthreads();
    #pragma unroll
    for (int off = 128; off > 0; off >>= 1) {
        if (tid < off) sm[tid] += sm[tid + off];
        __syncthreads();
    }
    if (tid == 0) out[0] = sm[0] * (1.f / (float)B_SZ);
}

// ---------------------------------------------------------------------------
extern "C" void kernel_launch(void* const* d_in, const int* in_sizes, int n_in,
                              void* d_out, int out_size) {
    const float* x = (const float*)d_in[0];
    const float* w = (const float*)d_in[1];
    const int* tgt = (const int*)d_in[2];
    float* out = (float*)d_out;

    xnorm_kernel<<<B_SZ, 128>>>(x);
    wnorm_kernel<<<C_SZ / 8, 256>>>(w);
    dim3 grid(NT, B_SZ / NTILE_M);
    gemm_partial_kernel<<<grid, 256>>>(w);
    finalize_kernel<<<B_SZ, 256>>>(w, tgt);
    mean_kernel<<<1, 256>>>(out);
}

// round 4
// speedup vs baseline: 4.9854x; 4.9854x over previous
#include <cuda_runtime.h>
#include <cuda_bf16.h>
#include <math.h>
#include <stdint.h>

#define B_SZ 512
#define D_SZ 512
#define C_SZ 100000
#define BN 128
#define BM 128
#define BK 32
#define NK 16                      // 512/32
#define NTILES_N 782               // ceil(100000/128)
#define C_PAD (NTILES_N * BN)      // 100096
#define PITCH 40                   // halves per smem row (80B, 16B-aligned)
#define STAGE_HALVES (256 * PITCH) // A(128 rows)+B(128 rows)
#define S_SCALE 30.0f
#define LMAX 31.0f
#define COS_M 0.8775825618903728f
#define SIN_M 0.47942553860420300f

// ---------------- static device scratch -------------------------------------
__device__ __nv_bfloat16 g_wn[(size_t)C_PAD * D_SZ];   // normalized bf16 w (pad rows stay 0)
__device__ __nv_bfloat16 g_xnbf[B_SZ * D_SZ];
__device__ float g_xn[B_SZ * D_SZ];
__device__ float g_winv[C_SZ];
__device__ float g_rowsum[B_SZ];
__device__ float g_nll[B_SZ];

// ---------------- PTX helpers ------------------------------------------------
__device__ __forceinline__ uint32_t smem_u32(const void* p) {
    uint32_t a;
    asm("{ .reg .u64 t; cvta.to.shared.u64 t, %1; cvt.u32.u64 %0, t; }" : "=r"(a) : "l"(p));
    return a;
}
__device__ __forceinline__ void cp16(uint32_t dst, const void* src) {
    asm volatile("cp.async.cg.shared.global [%0], [%1], 16;" :: "r"(dst), "l"(src));
}
#define CP_COMMIT() asm volatile("cp.async.commit_group;" ::: "memory")
#define CP_WAIT(n)  asm volatile("cp.async.wait_group %0;" :: "n"(n) : "memory")

__device__ __forceinline__ void ldsm4(uint32_t* r, uint32_t addr) {
    asm volatile("ldmatrix.sync.aligned.m8n8.x4.shared.b16 {%0,%1,%2,%3}, [%4];"
        : "=r"(r[0]), "=r"(r[1]), "=r"(r[2]), "=r"(r[3]) : "r"(addr));
}
__device__ __forceinline__ void mma16816(float* d, const uint32_t* a, uint32_t b0, uint32_t b1) {
    asm volatile(
        "mma.sync.aligned.m16n8k16.row.col.f32.bf16.bf16.f32 "
        "{%0,%1,%2,%3}, {%4,%5,%6,%7}, {%8,%9}, {%0,%1,%2,%3};"
        : "+f"(d[0]), "+f"(d[1]), "+f"(d[2]), "+f"(d[3])
        : "r"(a[0]), "r"(a[1]), "r"(a[2]), "r"(a[3]), "r"(b0), "r"(b1));
}

// ---------------------------------------------------------------------------
// Kernel 1: normalize x rows -> g_xn (fp32) + g_xnbf (bf16); zero g_rowsum
// ---------------------------------------------------------------------------
__global__ void xnorm_kernel(const float* __restrict__ x) {
    const int row = blockIdx.x;
    const int tid = threadIdx.x;   // 128
    const float* xr = x + (size_t)row * D_SZ;

    float ss = 0.f;
    float v[4];
    #pragma unroll
    for (int i = 0; i < 4; i++) { v[i] = xr[tid + i * 128]; ss += v[i] * v[i]; }
    __shared__ float red[128];
    red[tid] = ss;
    __syncthreads();
    #pragma unroll
    for (int off = 64; off > 0; off >>= 1) {
        if (tid < off) red[tid] += red[tid + off];
        __syncthreads();
    }
    const float inv = 1.f / fmaxf(sqrtf(red[0]), 1e-12f);
    #pragma unroll
    for (int i = 0; i < 4; i++) {
        int d = tid + i * 128;
        float nv = v[i] * inv;
        g_xn[(size_t)row * D_SZ + d] = nv;
        g_xnbf[(size_t)row * D_SZ + d] = __float2bfloat16_rn(nv);
    }
    if (tid == 0) g_rowsum[row] = 0.f;
}

// ---------------------------------------------------------------------------
// Kernel 2: normalize weight rows + convert to bf16 (one warp per row)
// ---------------------------------------------------------------------------
__global__ void wconv_kernel(const float* __restrict__ w) {
    const int warp = threadIdx.x >> 5;
    const int lane = threadIdx.x & 31;
    const int c = blockIdx.x * 8 + warp;       // grid 12500 -> 100000 rows
    const float4* wr = reinterpret_cast<const float4*>(w + (size_t)c * D_SZ);

    float4 v[4];
    float ss = 0.f;
    #pragma unroll
    for (int i = 0; i < 4; i++) {
        v[i] = wr[lane + i * 32];
        ss += v[i].x * v[i].x + v[i].y * v[i].y + v[i].z * v[i].z + v[i].w * v[i].w;
    }
    #pragma unroll
    for (int m = 16; m > 0; m >>= 1)
        ss += __shfl_xor_sync(0xffffffffu, ss, m);
    const float inv = 1.f / fmaxf(sqrtf(ss), 1e-12f);
    if (lane == 0) g_winv[c] = inv;

    uint2* dst = reinterpret_cast<uint2*>(g_wn + (size_t)c * D_SZ);
    #pragma unroll
    for (int i = 0; i < 4; i++) {
        __nv_bfloat162 p0 = __floats2bfloat162_rn(v[i].x * inv, v[i].y * inv);
        __nv_bfloat162 p1 = __floats2bfloat162_rn(v[i].z * inv, v[i].w * inv);
        uint2 o;
        o.x = *reinterpret_cast<uint32_t*>(&p0);
        o.y = *reinterpret_cast<uint32_t*>(&p1);
        dst[lane + i * 32] = o;
    }
}

// ---------------------------------------------------------------------------
// Kernel 3: fused HMMA GEMM (cosine tile) + streaming exp-sum epilogue.
// CTA 128x128xK512, 2-stage cp.async, 8 warps (2 M x 4 N), warp tile 64x32.
// ---------------------------------------------------------------------------
__global__ void __launch_bounds__(256) gemm_fused_kernel() {
    __shared__ __align__(16) __nv_bfloat16 smem[2 * STAGE_HALVES];  // 40,960 B
    const int tid = threadIdx.x;
    const int warp = tid >> 5;
    const int lane = tid & 31;
    const int wm = warp & 1;
    const int wn = warp >> 1;
    const int n0 = blockIdx.x * BN;
    const int m0 = blockIdx.y * BM;
    const uint32_t sb = smem_u32(smem);

    // per-thread cp.async source/dst precompute: 4 chunks of 16B per stage
    const __nv_bfloat16* srcA0 = g_xnbf + (size_t)m0 * D_SZ;
    const __nv_bfloat16* srcB0 = g_wn + (size_t)n0 * D_SZ;

    float acc[4][4][4];
    #pragma unroll
    for (int a = 0; a < 4; a++)
        #pragma unroll
        for (int b = 0; b < 4; b++)
            #pragma unroll
            for (int c = 0; c < 4; c++) acc[a][b][c] = 0.f;

    // ldmatrix base offsets (halves) within a stage
    const int lrow = lane & 15;
    const int lcol = (lane >> 4) * 8;

    // ---- load helper (macro-ish lambda) ----
    auto load_stage = [&](int stage, int k0) {
        const uint32_t dst = sb + (uint32_t)stage * (STAGE_HALVES * 2);
        #pragma unroll
        for (int i = 0; i < 4; i++) {
            int c = tid + i * 256;           // 0..1023
            int row = (c >> 2) & 127;
            int piece = c & 3;
            if (c < 512) {
                cp16(dst + (uint32_t)(row * PITCH + piece * 8) * 2,
                     srcA0 + (size_t)row * D_SZ + k0 + piece * 8);
            } else {
                cp16(dst + (uint32_t)(128 * PITCH + row * PITCH + piece * 8) * 2,
                     srcB0 + (size_t)row * D_SZ + k0 + piece * 8);
            }
        }
    };

    load_stage(0, 0);
    CP_COMMIT();

    for (int k = 0; k < NK; k++) {
        if (k < NK - 1) { load_stage((k + 1) & 1, (k + 1) * BK); CP_COMMIT(); }
        if (k == NK - 1) { CP_WAIT(0); } else { CP_WAIT(1); }
        __syncthreads();

        const uint32_t aoff = sb + (uint32_t)(k & 1) * (STAGE_HALVES * 2);
        const uint32_t boff = aoff + 128 * PITCH * 2;
        #pragma unroll
        for (int kk = 0; kk < BK; kk += 16) {
            uint32_t af[4][4], bf[2][4];
            #pragma unroll
            for (int mt = 0; mt < 4; mt++)
                ldsm4(af[mt], aoff + (uint32_t)((wm * 64 + mt * 16 + lrow) * PITCH + kk + lcol) * 2);
            #pragma unroll
            for (int nt2 = 0; nt2 < 2; nt2++)
                ldsm4(bf[nt2], boff + (uint32_t)((wn * 32 + nt2 * 16 + lrow) * PITCH + kk + lcol) * 2);
            #pragma unroll
            for (int mt = 0; mt < 4; mt++) {
                #pragma unroll
                for (int nt = 0; nt < 4; nt++) {
                    const uint32_t* bb = bf[nt >> 1];
                    uint32_t b0 = (nt & 1) ? bb[1] : bb[0];
                    uint32_t b1 = (nt & 1) ? bb[3] : bb[2];
                    mma16816(acc[mt][nt], af[mt], b0, b1);
                }
            }
        }
        __syncthreads();
    }

    // ---- epilogue: exp-sum per batch row, atomic into g_rowsum -------------
    const bool edge = (n0 + BN > C_SZ);
    const int rbase = m0 + wm * 64 + (lane >> 2);
    const int cbase = n0 + wn * 32 + 2 * (lane & 3);

    #pragma unroll
    for (int mt = 0; mt < 4; mt++) {
        float es0 = 0.f, es1 = 0.f;
        #pragma unroll
        for (int nt = 0; nt < 4; nt++) {
            const int c0 = cbase + nt * 8;
            if (!edge) {
                es0 += __expf(fmaf(acc[mt][nt][0], S_SCALE, -LMAX));
                es0 += __expf(fmaf(acc[mt][nt][1], S_SCALE, -LMAX));
                es1 += __expf(fmaf(acc[mt][nt][2], S_SCALE, -LMAX));
                es1 += __expf(fmaf(acc[mt][nt][3], S_SCALE, -LMAX));
            } else {
                if (c0 < C_SZ)     { es0 += __expf(fmaf(acc[mt][nt][0], S_SCALE, -LMAX));
                                     es1 += __expf(fmaf(acc[mt][nt][2], S_SCALE, -LMAX)); }
                if (c0 + 1 < C_SZ) { es0 += __expf(fmaf(acc[mt][nt][1], S_SCALE, -LMAX));
                                     es1 += __expf(fmaf(acc[mt][nt][3], S_SCALE, -LMAX)); }
            }
        }
        es0 += __shfl_xor_sync(0xffffffffu, es0, 1);
        es0 += __shfl_xor_sync(0xffffffffu, es0, 2);
        es1 += __shfl_xor_sync(0xffffffffu, es1, 1);
        es1 += __shfl_xor_sync(0xffffffffu, es1, 2);
        if ((lane & 3) == 0) {
            atomicAdd(&g_rowsum[rbase + mt * 16], es0);
            atomicAdd(&g_rowsum[rbase + mt * 16 + 8], es1);
        }
    }
}

// ---------------------------------------------------------------------------
// Kernel 4: finalize — exact fp32 target dot, margin swap, nll per row.
// (target is int32: JAX x64-disabled downcasts int64 -> int32)
// ---------------------------------------------------------------------------
__global__ void finalize_kernel(const float* __restrict__ w,
                                const int* __restrict__ tgt) {
    const int b = blockIdx.x;
    const int tid = threadIdx.x;   // 256
    __shared__ float sm[256];

    const int t = tgt[b];
    const float* wr = w + (size_t)t * D_SZ;
    const float* xr = g_xn + (size_t)b * D_SZ;
    sm[tid] = xr[tid] * wr[tid] + xr[tid + 256] * wr[tid + 256];
    __syncthreads();
    #pragma unroll
    for (int off = 128; off > 0; off >>= 1) {
        if (tid < off) sm[tid] += sm[tid + off];
        __syncthreads();
    }

    if (tid == 0) {
        float cosv = sm[0] * g_winv[t];
        float sinv = sqrtf(fmaxf(1.f - cosv * cosv, 0.f));
        float phi = cosv * COS_M - sinv * SIN_M;
        float adj = (cosv > 0.f) ? phi : cosv;          // easy margin
        float lt = S_SCALE * adj;
        float lo = S_SCALE * cosv;
        float s2 = g_rowsum[b] - expf(lo - LMAX) + expf(lt - LMAX);
        g_nll[b] = LMAX + logf(s2) - lt;
    }
}

// ---------------------------------------------------------------------------
// Kernel 5: mean over batch -> d_out[0]
// ---------------------------------------------------------------------------
__global__ void mean_kernel(float* __restrict__ out) {
    const int tid = threadIdx.x;   // 256
    __shared__ float sm[256];
    sm[tid] = g_nll[tid] + g_nll[tid + 256];
    __syncthreads();
    #pragma unroll
    for (int off = 128; off > 0; off >>= 1) {
        if (tid < off) sm[tid] += sm[tid + off];
        __syncthreads();
    }
    if (tid == 0) out[0] = sm[0] * (1.f / (float)B_SZ);
}

// ---------------------------------------------------------------------------
extern "C" void kernel_launch(void* const* d_in, const int* in_sizes, int n_in,
                              void* d_out, int out_size) {
    const float* x = (const float*)d_in[0];
    const float* w = (const float*)d_in[1];
    const int* tgt = (const int*)d_in[2];
    float* out = (float*)d_out;

    xnorm_kernel<<<B_SZ, 128>>>(x);
    wconv_kernel<<<C_SZ / 8, 256>>>(w);
    dim3 grid(NTILES_N, B_SZ / BM);
    gemm_fused_kernel<<<grid, 256>>>();
    finalize_kernel<<<B_SZ, 256>>>(w, tgt);
    mean_kernel<<<1, 256>>>(out);
}